// round 1
// baseline (speedup 1.0000x reference)
#include <cuda_runtime.h>
#include <cuda_bf16.h>

#define DM 1024        // d_model
#define BB 1024        // batch
#define FFS 2048       // small ffn
#define FFE 8192       // expert ffn
#define STEPS 3
#define LN_EPS 1e-5f

// ---------------- scratch (device globals; no allocation allowed) ----------
__device__ float g_S[9ull * BB * DM];
__device__ float g_integ[9ull * BB * DM];
__device__ float g_xn[9ull * BB * DM];
__device__ float g_v[9ull * BB * DM];
__device__ float g_x[9ull * BB * DM];
__device__ float g_xn2[9ull * BB * DM];
__device__ float g_mem[4ull * BB * DM];
__device__ float g_hs[5ull * BB * FFS];
__device__ float g_he[4ull * BB * FFE];

// adjacency of 3x3 grid (static)
__constant__ int c_nbr[9][4] = {
    {1,3,-1,-1},{0,2,4,-1},{1,5,-1,-1},
    {0,4,6,-1},{1,3,5,7},{2,4,8,-1},
    {3,7,-1,-1},{4,6,8,-1},{5,7,-1,-1}};
__constant__ int c_nnb[9] = {2,3,2,3,4,3,2,3,2};

// ---------------- helpers ---------------------------------------------------
__device__ __forceinline__ float blk_sum256(float v) {
    __shared__ float sred[8];
#pragma unroll
    for (int o = 16; o > 0; o >>= 1) v += __shfl_xor_sync(0xffffffffu, v, o);
    if ((threadIdx.x & 31) == 0) sred[threadIdx.x >> 5] = v;
    __syncthreads();
    float t = sred[0] + sred[1] + sred[2] + sred[3]
            + sred[4] + sred[5] + sred[6] + sred[7];
    __syncthreads();
    return t;
}

// ---------------- init: S = 0 except node 4 = seed; mem = 0 ----------------
__global__ void k_init(const float* __restrict__ seed) {
    long i = (long)blockIdx.x * blockDim.x + threadIdx.x;
    const long nbd = (long)BB * DM;
    long node = i / nbd;
    float v = 0.f;
    if (node == 4) v = seed[i - 4 * nbd];
    g_S[i] = v;
    if (i < 4 * nbd) g_mem[i] = 0.f;
}

// ------------- adjacency sum + LayerNorm1: one block per (node,b) row -------
__global__ void k_adj_ln(const float* __restrict__ lns,
                         const float* __restrict__ lnb) {
    int row  = blockIdx.x;          // 0..9*BB-1
    int node = row / BB;
    int b    = row % BB;
    int t    = threadIdx.x;         // 256, each does 4 floats
    long off = (long)row * DM;

    float4 acc = make_float4(0.f, 0.f, 0.f, 0.f);
    int nn = c_nnb[node];
#pragma unroll 4
    for (int i = 0; i < 4; i++) {
        if (i < nn) {
            int nb = c_nbr[node][i];
            float4 v = ((const float4*)(g_S + ((long)nb * BB + b) * DM))[t];
            acc.x += v.x; acc.y += v.y; acc.z += v.z; acc.w += v.w;
        }
    }
    ((float4*)(g_integ + off))[t] = acc;

    float mu = blk_sum256(acc.x + acc.y + acc.z + acc.w) * (1.f / DM);
    float dx = acc.x - mu, dy = acc.y - mu, dz = acc.z - mu, dw = acc.w - mu;
    float var = blk_sum256(dx*dx + dy*dy + dz*dz + dw*dw) * (1.f / DM);
    float r = rsqrtf(var + LN_EPS);

    float4 sc = ((const float4*)(lns + (long)node * DM))[t];
    float4 bi = ((const float4*)(lnb + (long)node * DM))[t];
    float4 o;
    o.x = dx * r * sc.x + bi.x;
    o.y = dy * r * sc.y + bi.y;
    o.z = dz * r * sc.z + bi.z;
    o.w = dw * r * sc.w + bi.w;
    ((float4*)(g_xn + off))[t] = o;
}

// ------------- memory blend + LayerNorm2 ------------------------------------
__global__ void k_mem_ln2(const float* __restrict__ lns,
                          const float* __restrict__ lnb) {
    int row  = blockIdx.x;
    int node = row / BB;
    int b    = row % BB;
    int t    = threadIdx.x;
    long off = (long)row * DM;

    float4 v = ((float4*)(g_x + off))[t];
    int slot = (node == 0) ? 0 : (node == 2) ? 1 : (node == 6) ? 2 : (node == 8) ? 3 : -1;
    if (slot >= 0) {
        long moff = ((long)slot * BB + b) * DM;
        float4 m = ((float4*)(g_mem + moff))[t];
        v.x = 0.7f * m.x + 0.3f * v.x;
        v.y = 0.7f * m.y + 0.3f * v.y;
        v.z = 0.7f * m.z + 0.3f * v.z;
        v.w = 0.7f * m.w + 0.3f * v.w;
        ((float4*)(g_mem + moff))[t] = v;
        ((float4*)(g_x + off))[t]   = v;
    }

    float mu = blk_sum256(v.x + v.y + v.z + v.w) * (1.f / DM);
    float dx = v.x - mu, dy = v.y - mu, dz = v.z - mu, dw = v.w - mu;
    float var = blk_sum256(dx*dx + dy*dy + dz*dz + dw*dw) * (1.f / DM);
    float r = rsqrtf(var + LN_EPS);

    float4 sc = ((const float4*)(lns + (long)node * DM))[t];
    float4 bi = ((const float4*)(lnb + (long)node * DM))[t];
    float4 o;
    o.x = dx * r * sc.x + bi.x;
    o.y = dy * r * sc.y + bi.y;
    o.z = dz * r * sc.z + bi.z;
    o.w = dw * r * sc.w + bi.w;
    ((float4*)(g_xn2 + off))[t] = o;
}

// ------------- generic batched NT GEMM: C = A(MxK) * W(NxK)^T + bias --------
// A node index  = bz*aMul + aAdd ;  C/addend node = bz*cMul + cAdd
// W/bias index  = bz (compact)
__global__ __launch_bounds__(256)
void gemm_nt(const float* __restrict__ A, long aStride, int aMul, int aAdd,
             const float* __restrict__ W, long wStride,
             const float* __restrict__ bias,
             float* __restrict__ C, long cStride, int cMul, int cAdd,
             const float* __restrict__ addend, long addStride,
             int N, int K, int relu) {
    __shared__ float As[16][128 + 4];
    __shared__ float Ws[16][128 + 4];

    int bz = blockIdx.z;
    int na = bz * aMul + aAdd;
    int nc = bz * cMul + cAdd;

    const float* Ab = A + (long)na * aStride + (long)blockIdx.y * 128 * K;
    const float* Wb = W + (long)bz * wStride + (long)blockIdx.x * 128 * K;
    const float* biasB = bias + (long)bz * N + blockIdx.x * 128;
    float* Cb = C + (long)nc * cStride + (long)blockIdx.y * 128 * N + blockIdx.x * 128;
    const float* Addb = addend
        ? addend + (long)nc * addStride + (long)blockIdx.y * 128 * N + blockIdx.x * 128
        : nullptr;

    int tid = threadIdx.x;
    int lr = tid >> 2;           // 0..63
    int lc = (tid & 3) * 4;      // 0,4,8,12

    float acc[8][8];
#pragma unroll
    for (int i = 0; i < 8; i++)
#pragma unroll
        for (int j = 0; j < 8; j++) acc[i][j] = 0.f;

    for (int kt = 0; kt < K; kt += 16) {
#pragma unroll
        for (int h = 0; h < 2; h++) {
            int r = lr + h * 64;
            float4 av = *(const float4*)(Ab + (long)r * K + kt + lc);
            As[lc + 0][r] = av.x; As[lc + 1][r] = av.y;
            As[lc + 2][r] = av.z; As[lc + 3][r] = av.w;
            float4 wv = *(const float4*)(Wb + (long)r * K + kt + lc);
            Ws[lc + 0][r] = wv.x; Ws[lc + 1][r] = wv.y;
            Ws[lc + 2][r] = wv.z; Ws[lc + 3][r] = wv.w;
        }
        __syncthreads();

        int tx = tid & 15, ty = tid >> 4;
#pragma unroll
        for (int k = 0; k < 16; k++) {
            float a[8], bv[8];
#pragma unroll
            for (int i = 0; i < 8; i++) a[i]  = As[k][ty * 8 + i];
#pragma unroll
            for (int j = 0; j < 8; j++) bv[j] = Ws[k][tx * 8 + j];
#pragma unroll
            for (int i = 0; i < 8; i++)
#pragma unroll
                for (int j = 0; j < 8; j++) acc[i][j] += a[i] * bv[j];
        }
        __syncthreads();
    }

    int tx = tid & 15, ty = tid >> 4;
    float4 bb0 = *(const float4*)(biasB + tx * 8);
    float4 bb1 = *(const float4*)(biasB + tx * 8 + 4);
#pragma unroll
    for (int i = 0; i < 8; i++) {
        long rowOff = (long)(ty * 8 + i) * N + tx * 8;
        float4 o0, o1;
        o0.x = acc[i][0] + bb0.x; o0.y = acc[i][1] + bb0.y;
        o0.z = acc[i][2] + bb0.z; o0.w = acc[i][3] + bb0.w;
        o1.x = acc[i][4] + bb1.x; o1.y = acc[i][5] + bb1.y;
        o1.z = acc[i][6] + bb1.z; o1.w = acc[i][7] + bb1.w;
        if (Addb) {
            float4 a0 = *(const float4*)(Addb + rowOff);
            float4 a1 = *(const float4*)(Addb + rowOff + 4);
            o0.x += a0.x; o0.y += a0.y; o0.z += a0.z; o0.w += a0.w;
            o1.x += a1.x; o1.y += a1.y; o1.z += a1.z; o1.w += a1.w;
        }
        if (relu) {
            o0.x = fmaxf(o0.x, 0.f); o0.y = fmaxf(o0.y, 0.f);
            o0.z = fmaxf(o0.z, 0.f); o0.w = fmaxf(o0.w, 0.f);
            o1.x = fmaxf(o1.x, 0.f); o1.y = fmaxf(o1.y, 0.f);
            o1.z = fmaxf(o1.z, 0.f); o1.w = fmaxf(o1.w, 0.f);
        }
        *(float4*)(Cb + rowOff)     = o0;
        *(float4*)(Cb + rowOff + 4) = o1;
    }
}

// ------------- output copy --------------------------------------------------
__global__ void k_copy_out(float* __restrict__ out) {
    long i = (long)blockIdx.x * blockDim.x + threadIdx.x;
    ((float4*)out)[i] = ((const float4*)g_S)[i];
}

// ---------------- launch ----------------------------------------------------
extern "C" void kernel_launch(void* const* d_in, const int* in_sizes, int n_in,
                              void* d_out, int out_size) {
    const float* seed  = (const float*)d_in[0];
    const float* ln1_s = (const float*)d_in[1];
    const float* ln1_b = (const float*)d_in[2];
    const float* v_w   = (const float*)d_in[3];
    const float* v_b   = (const float*)d_in[4];
    const float* o_w   = (const float*)d_in[5];
    const float* o_b   = (const float*)d_in[6];
    const float* ln2_s = (const float*)d_in[7];
    const float* ln2_b = (const float*)d_in[8];
    const float* w1_s  = (const float*)d_in[9];
    const float* b1_s  = (const float*)d_in[10];
    const float* w2_s  = (const float*)d_in[11];
    const float* b2_s  = (const float*)d_in[12];
    const float* w1_e  = (const float*)d_in[13];
    const float* b1_e  = (const float*)d_in[14];
    const float* w2_e  = (const float*)d_in[15];
    const float* b2_e  = (const float*)d_in[16];
    (void)in_sizes; (void)n_in;

    float *p_S, *p_integ, *p_xn, *p_v, *p_x, *p_xn2, *p_hs, *p_he;
    cudaGetSymbolAddress((void**)&p_S,     g_S);
    cudaGetSymbolAddress((void**)&p_integ, g_integ);
    cudaGetSymbolAddress((void**)&p_xn,    g_xn);
    cudaGetSymbolAddress((void**)&p_v,     g_v);
    cudaGetSymbolAddress((void**)&p_x,     g_x);
    cudaGetSymbolAddress((void**)&p_xn2,   g_xn2);
    cudaGetSymbolAddress((void**)&p_hs,    g_hs);
    cudaGetSymbolAddress((void**)&p_he,    g_he);

    const long ND = (long)BB * DM;

    k_init<<<(9 * BB * DM) / 256, 256>>>(seed);

    for (int s = 0; s < STEPS; s++) {
        // integ = A @ S ; xn = LN1(integ)
        k_adj_ln<<<9 * BB, 256>>>(ln1_s, ln1_b);

        // v = xn @ v_w^T + v_b
        gemm_nt<<<dim3(DM / 128, BB / 128, 9), 256>>>(
            p_xn, ND, 1, 0, v_w, (long)DM * DM, v_b,
            p_v, ND, 1, 0, nullptr, 0, DM, DM, 0);

        // x = integ + (v @ o_w^T + o_b)
        gemm_nt<<<dim3(DM / 128, BB / 128, 9), 256>>>(
            p_v, ND, 1, 0, o_w, (long)DM * DM, o_b,
            p_x, ND, 1, 0, p_integ, ND, DM, DM, 0);

        // memory blend + xn2 = LN2(x)
        k_mem_ln2<<<9 * BB, 256>>>(ln2_s, ln2_b);

        // hs = relu(xn2[sids] @ w1_s^T + b1_s)      sids = 2*bz
        gemm_nt<<<dim3(FFS / 128, BB / 128, 5), 256>>>(
            p_xn2, ND, 2, 0, w1_s, (long)FFS * DM, b1_s,
            p_hs, (long)BB * FFS, 1, 0, nullptr, 0, FFS, DM, 1);

        // S[sids] = x[sids] + hs @ w2_s^T + b2_s
        gemm_nt<<<dim3(DM / 128, BB / 128, 5), 256>>>(
            p_hs, (long)BB * FFS, 1, 0, w2_s, (long)DM * FFS, b2_s,
            p_S, ND, 2, 0, p_x, ND, DM, FFS, 0);

        // he = relu(xn2[eids] @ w1_e^T + b1_e)      eids = 2*bz+1
        gemm_nt<<<dim3(FFE / 128, BB / 128, 4), 256>>>(
            p_xn2, ND, 2, 1, w1_e, (long)FFE * DM, b1_e,
            p_he, (long)BB * FFE, 1, 0, nullptr, 0, FFE, DM, 1);

        // S[eids] = x[eids] + he @ w2_e^T + b2_e
        gemm_nt<<<dim3(DM / 128, BB / 128, 4), 256>>>(
            p_he, (long)BB * FFE, 1, 0, w2_e, (long)DM * FFE, b2_e,
            p_S, ND, 2, 1, p_x, ND, DM, FFE, 0);
    }

    k_copy_out<<<(9 * BB * DM / 4) / 256, 256>>>((float*)d_out);
}

// round 11
// speedup vs baseline: 3.1394x; 3.1394x over previous
#include <cuda_runtime.h>
#include <cuda_bf16.h>
#include <cstdint>

#define DM 1024
#define BB 1024
#define FFS 2048
#define FFE 8192
#define STEPS 3
#define LN_EPS 1e-5f

typedef __nv_bfloat16 bf16;
typedef __nv_bfloat162 bf162;

// ---------------- fp32 state (device globals) --------------------------------
__device__ __align__(256) float g_S[9ull * BB * DM];
__device__ __align__(256) float g_integ[9ull * BB * DM];
__device__ __align__(256) float g_x[9ull * BB * DM];
__device__ __align__(256) float g_mem[4ull * BB * DM];

// ---------------- packed hi/lo bf16 activations ------------------------------
// row-major rows; each row = K/32 chunks of 128B: [32 hi bf16 | 32 lo bf16]
__device__ __align__(256) bf16 g_xn_p [9ull * BB * 2 * DM];
__device__ __align__(256) bf16 g_v_p  [9ull * BB * 2 * DM];
__device__ __align__(256) bf16 g_xn2_p[9ull * BB * 2 * DM];
__device__ __align__(256) bf16 g_hs_p [5ull * BB * 2 * FFS];
__device__ __align__(256) bf16 g_he_p [4ull * BB * 2 * FFE];
// packed weights arena (offsets in bf16 elements)
#define OWP_VW  0ull
#define OWP_OW  18874368ull
#define OWP_W1S 37748736ull
#define OWP_W2S 58720256ull
#define OWP_W1E 79691776ull
#define OWP_W2E 146800640ull
#define OWP_TOT 213909504ull
__device__ __align__(256) bf16 g_wp[OWP_TOT];

__constant__ int c_nbr[9][4] = {
    {1,3,-1,-1},{0,2,4,-1},{1,5,-1,-1},
    {0,4,6,-1},{1,3,5,7},{2,4,8,-1},
    {3,7,-1,-1},{4,6,8,-1},{5,7,-1,-1}};
__constant__ int c_nnb[9] = {2,3,2,3,4,3,2,3,2};

// ---------------- helpers -----------------------------------------------------
__device__ __forceinline__ void split_store4(bf16* p, float x, float y, float z, float w) {
    bf16 hx = __float2bfloat16_rn(x), hy = __float2bfloat16_rn(y);
    bf16 hz = __float2bfloat16_rn(z), hw = __float2bfloat16_rn(w);
    bf162 h0; h0.x = hx; h0.y = hy;
    bf162 h1; h1.x = hz; h1.y = hw;
    bf162 l0; l0.x = __float2bfloat16_rn(x - __bfloat162float(hx));
    l0.y = __float2bfloat16_rn(y - __bfloat162float(hy));
    bf162 l1; l1.x = __float2bfloat16_rn(z - __bfloat162float(hz));
    l1.y = __float2bfloat16_rn(w - __bfloat162float(hw));
    *(bf162*)(p)      = h0;
    *(bf162*)(p + 2)  = h1;
    *(bf162*)(p + 32) = l0;
    *(bf162*)(p + 34) = l1;
}

__device__ __forceinline__ void cpa16(void* dst, const void* src) {
    uint32_t d;
    asm("{ .reg .u64 t; cvta.to.shared.u64 t, %1; cvt.u32.u64 %0, t; }"
        : "=r"(d) : "l"(dst));
    asm volatile("cp.async.cg.shared.global [%0], [%1], 16;"
                 :: "r"(d), "l"(__cvta_generic_to_global(src)) : "memory");
}
#define CPA_COMMIT() asm volatile("cp.async.commit_group;" ::: "memory")

// m16n8k16 bf16 HMMA, fp32 accumulate (sm_80+, compiles on every pass)
#define MMA16816(d, a0, a1, a2, a3, b0, b1) \
    asm volatile( \
        "mma.sync.aligned.m16n8k16.row.col.f32.bf16.bf16.f32 " \
        "{%0,%1,%2,%3}, {%4,%5,%6,%7}, {%8,%9}, {%0,%1,%2,%3};" \
        : "+f"((d)[0]), "+f"((d)[1]), "+f"((d)[2]), "+f"((d)[3]) \
        : "r"(a0), "r"(a1), "r"(a2), "r"(a3), "r"(b0), "r"(b1))

// ---------------- reductions --------------------------------------------------
__device__ __forceinline__ float blk_sum256(float v) {
    __shared__ float sred[8];
#pragma unroll
    for (int o = 16; o > 0; o >>= 1) v += __shfl_xor_sync(0xffffffffu, v, o);
    if ((threadIdx.x & 31) == 0) sred[threadIdx.x >> 5] = v;
    __syncthreads();
    float t = sred[0] + sred[1] + sred[2] + sred[3]
            + sred[4] + sred[5] + sred[6] + sred[7];
    __syncthreads();
    return t;
}

// ---------------- init / pack / copy -----------------------------------------
__global__ void k_init(const float* __restrict__ seed) {
    long i = (long)blockIdx.x * blockDim.x + threadIdx.x;
    const long nbd = (long)BB * DM;
    long node = i / nbd;
    float v = 0.f;
    if (node == 4) v = seed[i - 4 * nbd];
    g_S[i] = v;
    if (i < 4 * nbd) g_mem[i] = 0.f;
}

__global__ void k_pack(const float4* __restrict__ s, bf16* __restrict__ d,
                       int K, int n4) {
    int i = blockIdx.x * blockDim.x + threadIdx.x;
    if (i >= n4) return;
    float4 v = s[i];
    long e0 = (long)i * 4;
    long row = e0 / K;
    int  k   = (int)(e0 - row * K);
    bf16* p = d + row * (long)(2 * K) + (k >> 5) * 64 + (k & 31);
    split_store4(p, v.x, v.y, v.z, v.w);
}

__global__ void k_copy_out(float* __restrict__ out) {
    long i = (long)blockIdx.x * blockDim.x + threadIdx.x;
    ((float4*)out)[i] = ((const float4*)g_S)[i];
}

// ---------------- adjacency + LN1 -> packed xn --------------------------------
__global__ void k_adj_ln(const float* __restrict__ lns,
                         const float* __restrict__ lnb) {
    int row  = blockIdx.x;
    int node = row / BB;
    int b    = row % BB;
    int t    = threadIdx.x;
    long off = (long)row * DM;

    float4 acc = make_float4(0.f, 0.f, 0.f, 0.f);
    int nn = c_nnb[node];
#pragma unroll 4
    for (int i = 0; i < 4; i++) {
        if (i < nn) {
            int nb = c_nbr[node][i];
            float4 v = ((const float4*)(g_S + ((long)nb * BB + b) * DM))[t];
            acc.x += v.x; acc.y += v.y; acc.z += v.z; acc.w += v.w;
        }
    }
    ((float4*)(g_integ + off))[t] = acc;

    float mu = blk_sum256(acc.x + acc.y + acc.z + acc.w) * (1.f / DM);
    float dx = acc.x - mu, dy = acc.y - mu, dz = acc.z - mu, dw = acc.w - mu;
    float var = blk_sum256(dx*dx + dy*dy + dz*dz + dw*dw) * (1.f / DM);
    float r = rsqrtf(var + LN_EPS);

    float4 sc = ((const float4*)(lns + (long)node * DM))[t];
    float4 bi = ((const float4*)(lnb + (long)node * DM))[t];
    int col0 = 4 * t;
    bf16* p = g_xn_p + (long)row * (2 * DM) + (col0 >> 5) * 64 + (col0 & 31);
    split_store4(p,
        dx * r * sc.x + bi.x, dy * r * sc.y + bi.y,
        dz * r * sc.z + bi.z, dw * r * sc.w + bi.w);
}

// ---------------- memory blend + LN2 -> packed xn2 ----------------------------
__global__ void k_mem_ln2(const float* __restrict__ lns,
                          const float* __restrict__ lnb) {
    int row  = blockIdx.x;
    int node = row / BB;
    int b    = row % BB;
    int t    = threadIdx.x;
    long off = (long)row * DM;

    float4 v = ((float4*)(g_x + off))[t];
    int slot = (node == 0) ? 0 : (node == 2) ? 1 : (node == 6) ? 2 : (node == 8) ? 3 : -1;
    if (slot >= 0) {
        long moff = ((long)slot * BB + b) * DM;
        float4 m = ((float4*)(g_mem + moff))[t];
        v.x = 0.7f * m.x + 0.3f * v.x;
        v.y = 0.7f * m.y + 0.3f * v.y;
        v.z = 0.7f * m.z + 0.3f * v.z;
        v.w = 0.7f * m.w + 0.3f * v.w;
        ((float4*)(g_mem + moff))[t] = v;
        ((float4*)(g_x + off))[t]   = v;
    }

    float mu = blk_sum256(v.x + v.y + v.z + v.w) * (1.f / DM);
    float dx = v.x - mu, dy = v.y - mu, dz = v.z - mu, dw = v.w - mu;
    float var = blk_sum256(dx*dx + dy*dy + dz*dz + dw*dw) * (1.f / DM);
    float r = rsqrtf(var + LN_EPS);

    float4 sc = ((const float4*)(lns + (long)node * DM))[t];
    float4 bi = ((const float4*)(lnb + (long)node * DM))[t];
    int col0 = 4 * t;
    bf16* p = g_xn2_p + (long)row * (2 * DM) + (col0 >> 5) * 64 + (col0 & 31);
    split_store4(p,
        dx * r * sc.x + bi.x, dy * r * sc.y + bi.y,
        dz * r * sc.z + bi.z, dw * r * sc.w + bi.w);
}

// ---------------- GEMM: split-bf16 HMMA (mma.sync m16n8k16) -------------------
// Operands packed hi/lo: each row = K/32 chunks of 128B [32hi|32lo].
// 128x128 tile, 256 threads = 8 warps (2x4), warp tile 64x32.
// Per chunk (K=32): 2 k16 steps x 3 passes (hi*hi, hi*lo, lo*hi).
// smem per stage: Ahi/Alo/Bhi/Blo, each 128 rows x 32 cols bf16, row pitch 80B.
#define ST_A_LO 10240
#define ST_B_HI 20480
#define ST_B_LO 30720
#define ST_BYTES 40960
#define GSMEM (2 * ST_BYTES)

__global__ __launch_bounds__(256)
void gemm_hmma(const bf16* __restrict__ A, int aMul, int aAdd,
               const bf16* __restrict__ W,
               const float* __restrict__ bias,
               float* __restrict__ Cf, bf16* __restrict__ Cp,
               int cMul, int cAdd,
               const float* __restrict__ addend,
               int N, int K, int relu, int outPacked)
{
    extern __shared__ char smem[];
    const int tid  = threadIdx.x;
    const int wid  = tid >> 5;
    const int lane = tid & 31;
    const int bx = blockIdx.x, by = blockIdx.y, bz = blockIdx.z;
    const long ND_ = (long)BB * DM;
    const long rowB = (long)K * 4;   // bytes per packed row (2K bf16)

    const char* Ab = (const char*)A + ((long)(bz * aMul + aAdd) * BB + (long)by * 128) * rowB;
    const char* Wb = (const char*)W + ((long)bz * N + (long)bx * 128) * rowB;
    const int nodeC = bz * cMul + cAdd;

    const int wr = wid >> 2;         // warp row (0..1): rows wr*64..
    const int wc = wid & 3;          // warp col (0..3): cols wc*32..
    const int q  = lane >> 2;        // 0..7
    const int rr = lane & 3;         // 0..3

    const int nc = K >> 5;           // 32-K chunks

    // ---- stage loader: 2048 x 16B cp.async --------------------------------
    auto ldstage = [&](int c, int st) {
        char* base = smem + st * ST_BYTES;
#pragma unroll
        for (int i = 0; i < 8; i++) {
            int slot = tid + i * 256;            // 0..2047
            int half = slot >> 10;               // 0=A, 1=B
            int r    = (slot & 1023) >> 3;       // row 0..127
            int f    = slot & 7;                 // 16B unit in 128B row
            const char* src = (half ? Wb : Ab) + (long)r * rowB + (long)c * 128 + f * 16;
            char* dst = base + half * ST_B_HI + ((f >= 4) ? ST_A_LO : 0)
                      + r * 80 + (f & 3) * 16;
            cpa16(dst, src);
        }
        CPA_COMMIT();
    };

    float acc[4][4][4];
#pragma unroll
    for (int i = 0; i < 4; i++)
#pragma unroll
        for (int j = 0; j < 4; j++)
#pragma unroll
            for (int e = 0; e < 4; e++) acc[i][j][e] = 0.f;

    ldstage(0, 0);

    for (int c = 0; c < nc; ++c) {
        if (c + 1 < nc) {
            ldstage(c + 1, (c + 1) & 1);
            asm volatile("cp.async.wait_group 1;" ::: "memory");
        } else {
            asm volatile("cp.async.wait_group 0;" ::: "memory");
        }
        __syncthreads();

        const char* Sa  = smem + (c & 1) * ST_BYTES;
        const char* SaL = Sa + ST_A_LO;
        const char* Sb  = Sa + ST_B_HI;
        const char* SbL = Sa + ST_B_LO;

#pragma unroll
        for (int ks = 0; ks < 2; ks++) {
            const int kb = ks * 32 + 4 * rr;     // byte offset of col pair
            uint32_t bh[4][2], bl[4][2];
#pragma unroll
            for (int j = 0; j < 4; j++) {
                int brow = wc * 32 + j * 8 + q;
                const char* bp = Sb  + brow * 80 + kb;
                const char* lp = SbL + brow * 80 + kb;
                bh[j][0] = *(const uint32_t*)bp;
                bh[j][1] = *(const uint32_t*)(bp + 16);
                bl[j][0] = *(const uint32_t*)lp;
                bl[j][1] = *(const uint32_t*)(lp + 16);
            }
#pragma unroll
            for (int i = 0; i < 4; i++) {
                int arow = wr * 64 + i * 16 + q;
                const char* ap  = Sa  + arow * 80 + kb;
                const char* alp = SaL + arow * 80 + kb;
                uint32_t ah0 = *(const uint32_t*)ap;
                uint32_t ah1 = *(const uint32_t*)(ap + 640);     // +8 rows
                uint32_t ah2 = *(const uint32_t*)(ap + 16);      // +8 cols
                uint32_t ah3 = *(const uint32_t*)(ap + 656);
                uint32_t al0 = *(const uint32_t*)alp;
                uint32_t al1 = *(const uint32_t*)(alp + 640);
                uint32_t al2 = *(const uint32_t*)(alp + 16);
                uint32_t al3 = *(const uint32_t*)(alp + 656);
#pragma unroll
                for (int j = 0; j < 4; j++) {
                    MMA16816(acc[i][j], ah0, ah1, ah2, ah3, bh[j][0], bh[j][1]);
                    MMA16816(acc[i][j], ah0, ah1, ah2, ah3, bl[j][0], bl[j][1]);
                    MMA16816(acc[i][j], al0, al1, al2, al3, bh[j][0], bh[j][1]);
                }
            }
        }
        __syncthreads();
    }

    // ---- epilogue: fragment regs -> global --------------------------------
#pragma unroll
    for (int i = 0; i < 4; i++) {
#pragma unroll
        for (int j = 0; j < 4; j++) {
            int grow0 = by * 128 + wr * 64 + i * 16 + q;
            int gcol0 = bx * 128 + wc * 32 + j * 8 + 2 * rr;
            float2 bv = *(const float2*)&bias[(long)bz * N + gcol0];
#pragma unroll
            for (int h = 0; h < 2; h++) {
                int grow = grow0 + h * 8;
                float v0 = acc[i][j][h * 2 + 0] + bv.x;
                float v1 = acc[i][j][h * 2 + 1] + bv.y;
                if (addend) {
                    float2 ad = *(const float2*)
                        &addend[(long)nodeC * ND_ + (long)grow * N + gcol0];
                    v0 += ad.x; v1 += ad.y;
                }
                if (relu) { v0 = fmaxf(v0, 0.f); v1 = fmaxf(v1, 0.f); }
                if (outPacked) {
                    char* pc = (char*)Cp + ((long)nodeC * BB + grow) * (long)(N * 4)
                             + (gcol0 >> 5) * 128 + (gcol0 & 31) * 2;
                    bf16 h0 = __float2bfloat16_rn(v0);
                    bf16 h1 = __float2bfloat16_rn(v1);
                    bf162 hp; hp.x = h0; hp.y = h1;
                    bf162 lp;
                    lp.x = __float2bfloat16_rn(v0 - __bfloat162float(h0));
                    lp.y = __float2bfloat16_rn(v1 - __bfloat162float(h1));
                    *(bf162*)pc = hp;
                    *(bf162*)(pc + 64) = lp;
                } else {
                    float2 o; o.x = v0; o.y = v1;
                    *(float2*)&Cf[(long)nodeC * ND_ + (long)grow * N + gcol0] = o;
                }
            }
        }
    }
}

// ---------------- launch ------------------------------------------------------
extern "C" void kernel_launch(void* const* d_in, const int* in_sizes, int n_in,
                              void* d_out, int out_size) {
    const float* seed  = (const float*)d_in[0];
    const float* ln1_s = (const float*)d_in[1];
    const float* ln1_b = (const float*)d_in[2];
    const float* v_w   = (const float*)d_in[3];
    const float* v_b   = (const float*)d_in[4];
    const float* o_w   = (const float*)d_in[5];
    const float* o_b   = (const float*)d_in[6];
    const float* ln2_s = (const float*)d_in[7];
    const float* ln2_b = (const float*)d_in[8];
    const float* w1_s  = (const float*)d_in[9];
    const float* b1_s  = (const float*)d_in[10];
    const float* w2_s  = (const float*)d_in[11];
    const float* b2_s  = (const float*)d_in[12];
    const float* w1_e  = (const float*)d_in[13];
    const float* b1_e  = (const float*)d_in[14];
    const float* w2_e  = (const float*)d_in[15];
    const float* b2_e  = (const float*)d_in[16];
    (void)in_sizes; (void)n_in; (void)out_size;

    float *p_S, *p_integ, *p_x;
    bf16 *p_xn, *p_v, *p_xn2, *p_hs, *p_he, *p_wp;
    cudaGetSymbolAddress((void**)&p_S,     g_S);
    cudaGetSymbolAddress((void**)&p_integ, g_integ);
    cudaGetSymbolAddress((void**)&p_x,     g_x);
    cudaGetSymbolAddress((void**)&p_xn,    g_xn_p);
    cudaGetSymbolAddress((void**)&p_v,     g_v_p);
    cudaGetSymbolAddress((void**)&p_xn2,   g_xn2_p);
    cudaGetSymbolAddress((void**)&p_hs,    g_hs_p);
    cudaGetSymbolAddress((void**)&p_he,    g_he_p);
    cudaGetSymbolAddress((void**)&p_wp,    g_wp);

    cudaFuncSetAttribute(gemm_hmma, cudaFuncAttributeMaxDynamicSharedMemorySize, GSMEM);

    k_init<<<(9 * BB * DM) / 256, 256>>>(seed);

    // pack weights to hi/lo bf16 (per call; deterministic)
    k_pack<<<(2359296 + 255) / 256, 256>>>((const float4*)v_w,  p_wp + OWP_VW,  DM,  2359296);
    k_pack<<<(2359296 + 255) / 256, 256>>>((const float4*)o_w,  p_wp + OWP_OW,  DM,  2359296);
    k_pack<<<(2621440 + 255) / 256, 256>>>((const float4*)w1_s, p_wp + OWP_W1S, DM,  2621440);
    k_pack<<<(2621440 + 255) / 256, 256>>>((const float4*)w2_s, p_wp + OWP_W2S, FFS, 2621440);
    k_pack<<<(8388608 + 255) / 256, 256>>>((const float4*)w1_e, p_wp + OWP_W1E, DM,  8388608);
    k_pack<<<(8388608 + 255) / 256, 256>>>((const float4*)w2_e, p_wp + OWP_W2E, FFE, 8388608);

    for (int s = 0; s < STEPS; s++) {
        k_adj_ln<<<9 * BB, 256>>>(ln1_s, ln1_b);

        // v = xn @ v_w^T + v_b   (packed out)
        gemm_hmma<<<dim3(DM / 128, BB / 128, 9), 256, GSMEM>>>(
            p_xn, 1, 0, p_wp + OWP_VW, v_b,
            nullptr, p_v, 1, 0, nullptr, DM, DM, 0, 1);

        // x = integ + (v @ o_w^T + o_b)   (fp32 out)
        gemm_hmma<<<dim3(DM / 128, BB / 128, 9), 256, GSMEM>>>(
            p_v, 1, 0, p_wp + OWP_OW, o_b,
            p_x, nullptr, 1, 0, p_integ, DM, DM, 0, 0);

        k_mem_ln2<<<9 * BB, 256>>>(ln2_s, ln2_b);

        // hs = relu(xn2[2z] @ w1_s^T + b1_s)   (packed out)
        gemm_hmma<<<dim3(FFS / 128, BB / 128, 5), 256, GSMEM>>>(
            p_xn2, 2, 0, p_wp + OWP_W1S, b1_s,
            nullptr, p_hs, 1, 0, nullptr, FFS, DM, 1, 1);

        // S[2z] = x[2z] + hs @ w2_s^T + b2_s
        gemm_hmma<<<dim3(DM / 128, BB / 128, 5), 256, GSMEM>>>(
            p_hs, 1, 0, p_wp + OWP_W2S, b2_s,
            p_S, nullptr, 2, 0, p_x, DM, FFS, 0, 0);

        // he = relu(xn2[2z+1] @ w1_e^T + b1_e)   (packed out)
        gemm_hmma<<<dim3(FFE / 128, BB / 128, 4), 256, GSMEM>>>(
            p_xn2, 2, 1, p_wp + OWP_W1E, b1_e,
            nullptr, p_he, 1, 0, nullptr, FFE, DM, 1, 1);

        // S[2z+1] = x[2z+1] + he @ w2_e^T + b2_e
        gemm_hmma<<<dim3(DM / 128, BB / 128, 4), 256, GSMEM>>>(
            p_he, 1, 0, p_wp + OWP_W2E, b2_e,
            p_S, nullptr, 2, 1, p_x, DM, FFE, 0, 0);
    }

    k_copy_out<<<(9 * BB * DM / 4) / 256, 256>>>((float*)d_out);
}